// round 10
// baseline (speedup 1.0000x reference)
#include <cuda_runtime.h>
#include <cuda_bf16.h>

#define B_ 64
#define T_ 1024
#define I_ 8
#define H_ 512
#define O_ 2
#define NOISE_STD_ 0.05f
#define ALPHA_ 0.2f

#define NT_   128           // 4 warps, one batch per CTA
#define UPT_  4             // hidden units per thread
#define NW_   4

#define SA_   131072.0f     // 2^17 fixed-point scale for recurrence dots (R4 exact)
#define SO_   2097152.0f    // 2^21 fixed-point scale for output dots

// Single-MUFU tanh (~6e-4 rel err; net kernel rel_err ~1e-5, traj-dominated).
__device__ __forceinline__ float tanh_mufu(float x) {
    float r; asm("tanh.approx.f32 %0, %1;" : "=f"(r) : "f"(x)); return r;
}

// Warp-wide integer add-reduction (s32 redux supported on sm_103).
__device__ __forceinline__ int redux_add_s32(int v) {
    int r; asm("redux.sync.add.s32 %0, %1, 0xffffffff;" : "=r"(r) : "r"(v)); return r;
}

__global__ __launch_bounds__(NT_, 1)
void lowrank_rnn_kernel(const float* __restrict__ input,   // (B,T,I)
                        const float* __restrict__ noise,   // (B,T,H)
                        const float* __restrict__ wi,      // (I,H)
                        const float* __restrict__ si,      // (I,)
                        const float* __restrict__ m,       // (H,R)
                        const float* __restrict__ n,       // (H,R)
                        const float* __restrict__ wo,      // (H,O)
                        const float* __restrict__ so,      // (O,)
                        const float* __restrict__ h0,      // (H,)
                        float* __restrict__ out,           // (B,T,O)
                        float* __restrict__ traj)          // (B,T,H)
{
    __shared__ int2 s_obuf[T_][NW_];   // 32 KB: per-step per-warp o partials
    __shared__ int2 s_a[2][NW_];       // a-pair exchange, double-buffered

    const int b    = blockIdx.x;
    const int tid  = threadIdx.x;
    const int warp = tid >> 5;
    const int lane = tid & 31;
    const int k0   = tid * UPT_;

    // ---- per-thread weights (folded constants, identical to R4) ----
    float wif[I_][UPT_];
    #pragma unroll
    for (int i = 0; i < I_; ++i) {
        const float4 w = *(const float4*)(wi + i * H_ + k0);
        const float  s = si[i];
        wif[i][0] = w.x * s; wif[i][1] = w.y * s;
        wif[i][2] = w.z * s; wif[i][3] = w.w * s;
    }
    const float cm  = (ALPHA_ / (float)H_) / SA_;  // alpha/H and 1/Sa folded into m
    const float so0 = (so[0] / (float)H_) * SO_;   // 1/H and So folded into wo
    const float so1 = (so[1] / (float)H_) * SO_;
    float m0f[UPT_], m1f[UPT_], n0f[UPT_], n1f[UPT_], wo0f[UPT_], wo1f[UPT_];
    #pragma unroll
    for (int j = 0; j < UPT_; ++j) {
        const int k = k0 + j;
        m0f[j]  = m[k * 2 + 0] * cm;        m1f[j]  = m[k * 2 + 1] * cm;
        n0f[j]  = n[k * 2 + 0] * SA_;       n1f[j]  = n[k * 2 + 1] * SA_;
        wo0f[j] = wo[k * 2 + 0] * so0;      wo1f[j] = wo[k * 2 + 1] * so1;
    }

    float h[UPT_];
    {
        const float4 hh = *(const float4*)(h0 + k0);
        h[0] = hh.x; h[1] = hh.y; h[2] = hh.z; h[3] = hh.w;
    }

    const float* nz_base   = noise + (size_t)b * T_ * H_ + k0;
    const float* in_base   = input + (size_t)b * T_ * I_;
    float*       traj_base = traj  + (size_t)b * T_ * H_ + k0;
    float*       out_base  = out   + (size_t)b * T_ * O_;

    // ---- prefetch rings, depth 4: noise (per-thread) + input row (broadcast) ----
    float4 ring[4];
    float4 ir0[4], ir1[4];
    #pragma unroll
    for (int j = 0; j < 4; ++j) {
        ring[j] = *(const float4*)(nz_base + (size_t)j * H_);
        ir0[j]  = *(const float4*)(in_base + j * I_);
        ir1[j]  = *(const float4*)(in_base + j * I_ + 4);
    }

    // ---- pre-loop: a = n^T r_0 (buffer 1; loop iter 0 writes buffer 0) ----
    float a0, a1;
    {
        float pa0 = 0.0f, pa1 = 0.0f;
        #pragma unroll
        for (int u = 0; u < UPT_; ++u) {
            const float r = tanh_mufu(h[u]);
            pa0 = fmaf(r, n0f[u], pa0);
            pa1 = fmaf(r, n1f[u], pa1);
        }
        const int ia0 = redux_add_s32(__float2int_rn(pa0));
        const int ia1 = redux_add_s32(__float2int_rn(pa1));
        if (lane == 0) s_a[1][warp] = make_int2(ia0, ia1);
        __syncthreads();
        const int4* va = (const int4*)s_a[1];      // 2x LDS.128 covers 4 warps
        const int4 v0 = va[0], v1 = va[1];
        a0 = (float)((v0.x + v0.z) + (v1.x + v1.z));
        a1 = (float)((v0.y + v0.w) + (v1.y + v1.w));
    }

    // ---- main scan ----
    #pragma unroll 4
    for (int t = 0; t < T_; ++t) {
        const int j = t & 3;
        const float4 nz = ring[j];
        const float4 i0 = ir0[j];
        const float4 i1 = ir1[j];
        int tp = t + 4; if (tp > T_ - 1) tp = T_ - 1;            // clamp tail
        ring[j] = *(const float4*)(nz_base + (size_t)tp * H_);   // prefetch t+4
        ir0[j]  = *(const float4*)(in_base + tp * I_);
        ir1[j]  = *(const float4*)(in_base + tp * I_ + 4);

        // input projection p_t for 4 units (off critical path)
        float p[UPT_];
        #pragma unroll
        for (int u = 0; u < UPT_; ++u) {
            float pp = i0.x * wif[0][u];
            pp = fmaf(i0.y, wif[1][u], pp);
            pp = fmaf(i0.z, wif[2][u], pp);
            pp = fmaf(i0.w, wif[3][u], pp);
            pp = fmaf(i1.x, wif[4][u], pp);
            pp = fmaf(i1.y, wif[5][u], pp);
            pp = fmaf(i1.z, wif[6][u], pp);
            pp = fmaf(i1.w, wif[7][u], pp);
            p[u] = pp;
        }
        const float nza[UPT_] = {nz.x, nz.y, nz.z, nz.w};

        // h' = 0.8h + 0.05nz + 0.2p + a0*m0f + a1*m1f ; r' = tanh(h')
        float pa0 = 0.0f, pa1 = 0.0f, po0 = 0.0f, po1 = 0.0f;
        #pragma unroll
        for (int u = 0; u < UPT_; ++u) {
            const float base = fmaf(NOISE_STD_, nza[u], ALPHA_ * p[u]);  // off path
            const float hb   = fmaf(1.0f - ALPHA_, h[u], base);          // off path
            float hx = fmaf(a0, m0f[u], hb);                             // path: 2 FMA
            hx       = fmaf(a1, m1f[u], hx);
            h[u] = hx;
            const float r = tanh_mufu(hx);                               // 1 MUFU
            pa0 = fmaf(r, n0f[u], pa0);     // scaled by Sa
            pa1 = fmaf(r, n1f[u], pa1);
            po0 = fmaf(r, wo0f[u], po0);    // scaled by So
            po1 = fmaf(r, wo1f[u], po1);
        }

        // fixed-point warp reductions (a-pair on critical path, o-pair in shadow)
        const int ia0 = redux_add_s32(__float2int_rn(pa0));
        const int ia1 = redux_add_s32(__float2int_rn(pa1));
        const int io0 = redux_add_s32(__float2int_rn(po0));
        const int io1 = redux_add_s32(__float2int_rn(po1));

        const int buf = t & 1;
        if (lane == 0) {
            s_a[buf][warp]    = make_int2(ia0, ia1);
            s_obuf[t][warp]   = make_int2(io0, io1);   // deferred: consumed post-loop
        }
        __syncthreads();                  // one bar per step (no pending STG before it)

        // tiny cross-warp integer sum (2x LDS.128), all warps symmetric
        {
            const int4* va = (const int4*)s_a[buf];
            const int4 v0 = va[0], v1 = va[1];
            a0 = (float)((v0.x + v0.z) + (v1.x + v1.z));
            a1 = (float)((v0.y + v0.w) + (v1.y + v1.w));
        }

        // traj[t] = h_{t+1}: issued right AFTER the bar => a full step to drain
        // before the next bar (BAR.SYNC drains pending stores).
        *(float4*)(traj_base + (size_t)t * H_) = make_float4(h[0], h[1], h[2], h[3]);
    }

    // ---- post-loop: combine deferred o-partials and write out (parallel) ----
    __syncthreads();
    #pragma unroll
    for (int t = tid; t < T_; t += NT_) {          // 8 iterations per thread
        const int4* vo = (const int4*)s_obuf[t];   // 2x LDS.128
        const int4 v0 = vo[0], v1 = vo[1];
        const float o0 = (float)((v0.x + v0.z) + (v1.x + v1.z)) * (1.0f / SO_);
        const float o1 = (float)((v0.y + v0.w) + (v1.y + v1.w)) * (1.0f / SO_);
        *(float2*)(out_base + (size_t)t * O_) = make_float2(o0, o1);
    }
}

extern "C" void kernel_launch(void* const* d_in, const int* in_sizes, int n_in,
                              void* d_out, int out_size) {
    const float* input = (const float*)d_in[0];
    const float* noise = (const float*)d_in[1];
    const float* wi    = (const float*)d_in[2];
    const float* si    = (const float*)d_in[3];
    const float* m     = (const float*)d_in[4];
    const float* n     = (const float*)d_in[5];
    const float* wo    = (const float*)d_in[6];
    const float* so    = (const float*)d_in[7];
    const float* h0    = (const float*)d_in[8];

    float* out  = (float*)d_out;                         // (B,T,O) first
    float* traj = (float*)d_out + (size_t)B_ * T_ * O_;  // then (B,T,H)

    lowrank_rnn_kernel<<<B_, NT_>>>(input, noise, wi, si, m, n, wo, so, h0,
                                    out, traj);
}

// round 11
// speedup vs baseline: 1.1713x; 1.1713x over previous
#include <cuda_runtime.h>
#include <cuda_bf16.h>

#define B_ 64
#define T_ 1024
#define I_ 8
#define H_ 512
#define O_ 2
#define NOISE_STD_ 0.05f
#define ALPHA_ 0.2f

#define NT_   128           // scan: 4 warps, one batch per CTA
#define UPT_  4             // hidden units per thread
#define NW_   4
#define TC_   128           // pass-1 timesteps per CTA (grid.y = T_/TC_ = 8)

#define SA_      8192.0f    // 2^13 scale for recurrence dots (magic-window safe, R6-proven)
#define SO_      2097152.0f // 2^21 scale for output dots
#define MAGIC_F  12582912.0f    // 2^23 + 2^22 round-to-int bias
// Warp biased sum = 32*0x4B400000 + S = 0x68000000 + S (mod 2^32).
// 4 warps -> 0xA0000000 + S. Re-bias to float-int: + (0x4B400000 - 0xA0000000).
#define REBIAS_I ((int)0xAB400000u)

// ---- 128 MB device scratch: e(b,t,k) = 0.05*noise + alpha*(x . Wi*si) ----
__device__ float g_e[(size_t)B_ * T_ * H_];

// Single-MUFU tanh (~6e-4 rel err; net kernel rel_err ~1e-5, traj-dominated).
__device__ __forceinline__ float tanh_mufu(float x) {
    float r; asm("tanh.approx.f32 %0, %1;" : "=f"(r) : "f"(x)); return r;
}

// Warp-wide integer add-reduction (s32 redux supported on sm_103).
__device__ __forceinline__ int redux_add_s32(int v) {
    int r; asm("redux.sync.add.s32 %0, %1, 0xffffffff;" : "=r"(r) : "r"(v)); return r;
}

// ================= Pass 1: precompute e = 0.05*nz + alpha*proj =================
__global__ __launch_bounds__(NT_, 8)
void precompute_e_kernel(const float* __restrict__ input,   // (B,T,I)
                         const float* __restrict__ noise,   // (B,T,H)
                         const float* __restrict__ wi,      // (I,H)
                         const float* __restrict__ si)      // (I,)
{
    const int b   = blockIdx.x;
    const int t0  = blockIdx.y * TC_;
    const int tid = threadIdx.x;
    const int k0  = tid * UPT_;

    // per-thread folded weights: wi*si*alpha for this thread's 4 hidden units
    float wif[I_][UPT_];
    #pragma unroll
    for (int i = 0; i < I_; ++i) {
        const float4 w = *(const float4*)(wi + i * H_ + k0);
        const float  s = si[i] * ALPHA_;
        wif[i][0] = w.x * s; wif[i][1] = w.y * s;
        wif[i][2] = w.z * s; wif[i][3] = w.w * s;
    }

    const float* in_base = input + (size_t)b * T_ * I_;
    const float* nz_base = noise + (size_t)b * T_ * H_ + k0;
    float*       e_base  = g_e   + (size_t)b * T_ * H_ + k0;

    #pragma unroll 2
    for (int tt = 0; tt < TC_; ++tt) {
        const int t = t0 + tt;
        const float4 x0 = __ldg((const float4*)(in_base + t * I_));
        const float4 x1 = __ldg((const float4*)(in_base + t * I_ + 4));
        const float4 nz = *(const float4*)(nz_base + (size_t)t * H_);
        const float nza[UPT_] = {nz.x, nz.y, nz.z, nz.w};
        float e[UPT_];
        #pragma unroll
        for (int u = 0; u < UPT_; ++u) {
            float pp = fmaf(NOISE_STD_, nza[u], x0.x * wif[0][u]);
            pp = fmaf(x0.y, wif[1][u], pp);
            pp = fmaf(x0.z, wif[2][u], pp);
            pp = fmaf(x0.w, wif[3][u], pp);
            pp = fmaf(x1.x, wif[4][u], pp);
            pp = fmaf(x1.y, wif[5][u], pp);
            pp = fmaf(x1.z, wif[6][u], pp);
            pp = fmaf(x1.w, wif[7][u], pp);
            e[u] = pp;
        }
        *(float4*)(e_base + (size_t)t * H_) = make_float4(e[0], e[1], e[2], e[3]);
    }
}

// ================= Pass 2: the scan (R4 structure, slimmed) =================
__global__ __launch_bounds__(NT_, 1)
void lowrank_rnn_kernel(const float* __restrict__ m,       // (H,R)
                        const float* __restrict__ n,       // (H,R)
                        const float* __restrict__ wo,      // (H,O)
                        const float* __restrict__ so,      // (O,)
                        const float* __restrict__ h0,      // (H,)
                        float* __restrict__ out,           // (B,T,O)
                        float* __restrict__ traj)          // (B,T,H)
{
    __shared__ int4 s_red[2][NW_];           // (a0b, a1b, o0, o1) per warp, dbl-buffered

    const int b    = blockIdx.x;
    const int tid  = threadIdx.x;
    const int warp = tid >> 5;
    const int lane = tid & 31;
    const int k0   = tid * UPT_;

    // ---- per-thread weights (folded constants) ----
    const float cm  = (ALPHA_ / (float)H_) / SA_;  // alpha/H and 1/Sa folded into m
    const float so0 = (so[0] / (float)H_) * SO_;   // 1/H and So folded into wo
    const float so1 = (so[1] / (float)H_) * SO_;
    float m0f[UPT_], m1f[UPT_], n0f[UPT_], n1f[UPT_], wo0f[UPT_], wo1f[UPT_];
    float negmc[UPT_];     // -(MAGIC)*(m0f+m1f): cancels bias carried in A0b/A1b
    #pragma unroll
    for (int j = 0; j < UPT_; ++j) {
        const int k = k0 + j;
        m0f[j]  = m[k * 2 + 0] * cm;        m1f[j]  = m[k * 2 + 1] * cm;
        n0f[j]  = n[k * 2 + 0] * SA_;       n1f[j]  = n[k * 2 + 1] * SA_;
        wo0f[j] = wo[k * 2 + 0] * so0;      wo1f[j] = wo[k * 2 + 1] * so1;
        negmc[j] = -MAGIC_F * (m0f[j] + m1f[j]);
    }

    float h[UPT_];
    {
        const float4 hh = *(const float4*)(h0 + k0);
        h[0] = hh.x; h[1] = hh.y; h[2] = hh.z; h[3] = hh.w;
    }

    const float* e_base    = g_e  + (size_t)b * T_ * H_ + k0;
    float*       traj_base = traj + (size_t)b * T_ * H_ + k0;
    float*       out_base  = out  + (size_t)b * T_ * O_;

    // ---- e prefetch ring, depth 4 (the only per-step memory read) ----
    float4 ring[4];
    #pragma unroll
    for (int j = 0; j < 4; ++j)
        ring[j] = *(const float4*)(e_base + (size_t)j * H_);

    // ---- pre-loop: biased a(0) from r = tanh(h0) (buffer 1) ----
    float A0b, A1b;      // carry +MAGIC_F bias each
    {
        float pa0 = 0.0f, pa1 = 0.0f;
        #pragma unroll
        for (int u = 0; u < UPT_; ++u) {
            const float r = tanh_mufu(h[u]);
            pa0 = fmaf(r, n0f[u], pa0);
            pa1 = fmaf(r, n1f[u], pa1);
        }
        const int W0 = redux_add_s32(__float_as_int(pa0 + MAGIC_F));
        const int W1 = redux_add_s32(__float_as_int(pa1 + MAGIC_F));
        if (lane == 0) s_red[1][warp] = make_int4(W0, W1, 0, 0);
        __syncthreads();
        int sx = 0, sy = 0;
        #pragma unroll
        for (int w = 0; w < NW_; ++w) {
            const int4 v = s_red[1][w];
            sx += v.x; sy += v.y;
        }
        A0b = __int_as_float(sx + REBIAS_I);
        A1b = __int_as_float(sy + REBIAS_I);
    }

    // ---- main scan ----
    #pragma unroll 4
    for (int t = 0; t < T_; ++t) {
        const int j = t & 3;
        const float4 e4 = ring[j];
        int tp = t + 4; if (tp > T_ - 1) tp = T_ - 1;            // clamp tail
        ring[j] = *(const float4*)(e_base + (size_t)tp * H_);    // prefetch t+4

        const float ea[UPT_] = {e4.x, e4.y, e4.z, e4.w};

        // h' = 0.8h + e + a0*m0f + a1*m1f (bias cancelled via negmc) ; r' = tanh
        float pa0 = 0.0f, pa1 = 0.0f, po0 = 0.0f, po1 = 0.0f;
        #pragma unroll
        for (int u = 0; u < UPT_; ++u) {
            const float hb = fmaf(1.0f - ALPHA_, h[u], ea[u] + negmc[u]);  // off path
            float hx = fmaf(A0b, m0f[u], hb);                              // path: 2 FMA
            hx       = fmaf(A1b, m1f[u], hx);
            h[u] = hx;
            const float r = tanh_mufu(hx);                                 // 1 MUFU
            pa0 = fmaf(r, n0f[u], pa0);     // scaled by Sa
            pa1 = fmaf(r, n1f[u], pa1);
            po0 = fmaf(r, wo0f[u], po0);    // scaled by So
            po1 = fmaf(r, wo1f[u], po1);
        }

        // traj[t] = h_{t+1}, coalesced STG.128 (R4 position: before reductions)
        *(float4*)(traj_base + (size_t)t * H_) = make_float4(h[0], h[1], h[2], h[3]);

        // warp reductions: magic-bias a-pair (FADD, no F2I); o-pair plain F2I
        const int W0 = redux_add_s32(__float_as_int(pa0 + MAGIC_F));
        const int W1 = redux_add_s32(__float_as_int(pa1 + MAGIC_F));
        const int U0 = redux_add_s32(__float2int_rn(po0));
        const int U1 = redux_add_s32(__float2int_rn(po1));

        const int buf = t & 1;
        if (lane == 0) s_red[buf][warp] = make_int4(W0, W1, U0, U1);
        __syncthreads();                  // one bar per step (double-buffered)

        // cross-warp combine: IADD tree + magic re-bias (no I2F on the path)
        const int4 v0 = s_red[buf][0];
        const int4 v1 = s_red[buf][1];
        const int4 v2 = s_red[buf][2];
        const int4 v3 = s_red[buf][3];
        A0b = __int_as_float(((v0.x + v1.x) + (v2.x + v3.x)) + REBIAS_I);
        A1b = __int_as_float(((v0.y + v1.y) + (v2.y + v3.y)) + REBIAS_I);

        if (tid == 0) {
            const float o0 = (float)((v0.z + v1.z) + (v2.z + v3.z)) * (1.0f / SO_);
            const float o1 = (float)((v0.w + v1.w) + (v2.w + v3.w)) * (1.0f / SO_);
            *(float2*)(out_base + (size_t)t * O_) = make_float2(o0, o1);
        }
    }
}

extern "C" void kernel_launch(void* const* d_in, const int* in_sizes, int n_in,
                              void* d_out, int out_size) {
    const float* input = (const float*)d_in[0];
    const float* noise = (const float*)d_in[1];
    const float* wi    = (const float*)d_in[2];
    const float* si    = (const float*)d_in[3];
    const float* m     = (const float*)d_in[4];
    const float* n     = (const float*)d_in[5];
    const float* wo    = (const float*)d_in[6];
    const float* so    = (const float*)d_in[7];
    const float* h0    = (const float*)d_in[8];

    float* out  = (float*)d_out;                         // (B,T,O) first
    float* traj = (float*)d_out + (size_t)B_ * T_ * O_;  // then (B,T,H)

    precompute_e_kernel<<<dim3(B_, T_ / TC_), NT_>>>(input, noise, wi, si);
    lowrank_rnn_kernel<<<B_, NT_>>>(m, n, wo, so, h0, out, traj);
}

// round 12
// speedup vs baseline: 1.3717x; 1.1711x over previous
#include <cuda_runtime.h>
#include <cuda_bf16.h>

#define B_ 64
#define T_ 1024
#define I_ 8
#define H_ 512
#define O_ 2
#define NOISE_STD_ 0.05f
#define ALPHA_ 0.2f

#define NT_   256           // 8 warps: 4 consumer + 4 producer
#define UPT_  4             // hidden units per thread (128 threads per role)
#define NCW_  4             // consumer warps
#define D_    4             // producer lookahead (steps)
#define RING_ 8             // smem e-ring slots
#define PF_   4             // producer LDG pipeline depth

#define SA_      8192.0f    // 2^13 scale for recurrence dots (magic-window safe)
#define SO_      2097152.0f // 2^21 scale for output dots
#define MAGIC_F  12582912.0f    // 2^23 + 2^22 round-to-int bias
// 4 consumer-warp biased sums: each 0x68000000 + S  =>  total 0xA0000000 + S.
// Re-bias to float-int: + (0x4B400000 - 0xA0000000) = 0xAB400000.
#define REBIAS_I ((int)0xAB400000u)

// Single-MUFU tanh (~6e-4 rel err; net kernel rel_err ~1e-5, traj-dominated).
__device__ __forceinline__ float tanh_mufu(float x) {
    float r; asm("tanh.approx.f32 %0, %1;" : "=f"(r) : "f"(x)); return r;
}
// Warp-wide integer add-reduction (s32 redux supported on sm_103).
__device__ __forceinline__ int redux_add_s32(int v) {
    int r; asm("redux.sync.add.s32 %0, %1, 0xffffffff;" : "=r"(r) : "r"(v)); return r;
}
// Full-CTA barrier usable from divergent (role-split) code paths.
__device__ __forceinline__ void cta_bar() {
    asm volatile("bar.sync 0, %0;" :: "n"(NT_) : "memory");
}

__global__ __launch_bounds__(NT_, 1)
void lowrank_rnn_kernel(const float* __restrict__ input,   // (B,T,I)
                        const float* __restrict__ noise,   // (B,T,H)
                        const float* __restrict__ wi,      // (I,H)
                        const float* __restrict__ si,      // (I,)
                        const float* __restrict__ m,       // (H,R)
                        const float* __restrict__ n,       // (H,R)
                        const float* __restrict__ wo,      // (H,O)
                        const float* __restrict__ so,      // (O,)
                        const float* __restrict__ h0,      // (H,)
                        float* __restrict__ out,           // (B,T,O)
                        float* __restrict__ traj)          // (B,T,H)
{
    __shared__ float s_e[RING_][H_];       // 16 KB: e(t) ring, lookahead D_
    __shared__ int4  s_red[2][NCW_];       // consumer exchange, dbl-buffered

    const int b   = blockIdx.x;
    const int tid = threadIdx.x;

    if (tid >= 128) {
        // ===================== PRODUCER role (warps 4-7) =====================
        const int ptid = tid - 128;
        const int k0   = ptid * UPT_;

        float wif[I_][UPT_];               // wi * si * alpha
        #pragma unroll
        for (int i = 0; i < I_; ++i) {
            const float4 w = *(const float4*)(wi + i * H_ + k0);
            const float  s = si[i] * ALPHA_;
            wif[i][0] = w.x * s; wif[i][1] = w.y * s;
            wif[i][2] = w.z * s; wif[i][3] = w.w * s;
        }
        const float* nz_base = noise + (size_t)b * T_ * H_ + k0;
        const float* in_base = input + (size_t)b * T_ * I_;

        // prologue: produce slots 0..D_-1 directly (latency OK here)
        #pragma unroll
        for (int s = 0; s < D_; ++s) {
            const float4 nz = *(const float4*)(nz_base + (size_t)s * H_);
            const float4 x0 = __ldg((const float4*)(in_base + s * I_));
            const float4 x1 = __ldg((const float4*)(in_base + s * I_ + 4));
            const float nza[UPT_] = {nz.x, nz.y, nz.z, nz.w};
            float e[UPT_];
            #pragma unroll
            for (int u = 0; u < UPT_; ++u) {
                float pp = fmaf(NOISE_STD_, nza[u], x0.x * wif[0][u]);
                pp = fmaf(x0.y, wif[1][u], pp);
                pp = fmaf(x0.z, wif[2][u], pp);
                pp = fmaf(x0.w, wif[3][u], pp);
                pp = fmaf(x1.x, wif[4][u], pp);
                pp = fmaf(x1.y, wif[5][u], pp);
                pp = fmaf(x1.z, wif[6][u], pp);
                pp = fmaf(x1.w, wif[7][u], pp);
                e[u] = pp;
            }
            *(float4*)&s_e[s][k0] = make_float4(e[0], e[1], e[2], e[3]);
        }
        // preload LDG ring for steps D_..D_+PF_-1
        float4 rnz[PF_], rx0[PF_], rx1[PF_];
        #pragma unroll
        for (int j = 0; j < PF_; ++j) {
            const int t = j + D_;          // 4..7, all < T_
            rnz[j] = *(const float4*)(nz_base + (size_t)t * H_);
            rx0[j] = __ldg((const float4*)(in_base + t * I_));
            rx1[j] = __ldg((const float4*)(in_base + t * I_ + 4));
        }
        cta_bar();                          // prologue barrier (matches consumer)

        #pragma unroll 4
        for (int t = 0; t < T_; ++t) {
            const int j  = t & (PF_ - 1);
            const int tp = t + D_;
            if (tp < T_) {                 // produce e(tp) into slot tp & 7
                const float4 nz = rnz[j];
                const float4 x0 = rx0[j];
                const float4 x1 = rx1[j];
                const float nza[UPT_] = {nz.x, nz.y, nz.z, nz.w};
                float e[UPT_];
                #pragma unroll
                for (int u = 0; u < UPT_; ++u) {
                    float pp = fmaf(NOISE_STD_, nza[u], x0.x * wif[0][u]);
                    pp = fmaf(x0.y, wif[1][u], pp);
                    pp = fmaf(x0.z, wif[2][u], pp);
                    pp = fmaf(x0.w, wif[3][u], pp);
                    pp = fmaf(x1.x, wif[4][u], pp);
                    pp = fmaf(x1.y, wif[5][u], pp);
                    pp = fmaf(x1.z, wif[6][u], pp);
                    pp = fmaf(x1.w, wif[7][u], pp);
                    e[u] = pp;
                }
                *(float4*)&s_e[tp & (RING_ - 1)][k0] =
                    make_float4(e[0], e[1], e[2], e[3]);
            }
            // refill LDG pipeline for step t + D_ + PF_ (clamped)
            int tl = t + D_ + PF_; if (tl > T_ - 1) tl = T_ - 1;
            rnz[j] = *(const float4*)(nz_base + (size_t)tl * H_);
            rx0[j] = __ldg((const float4*)(in_base + tl * I_));
            rx1[j] = __ldg((const float4*)(in_base + tl * I_ + 4));

            cta_bar();                      // per-step barrier
        }
    } else {
        // ===================== CONSUMER role (warps 0-3) =====================
        const int warp = tid >> 5;
        const int lane = tid & 31;
        const int k0   = tid * UPT_;

        const float cm  = (ALPHA_ / (float)H_) / SA_;
        const float so0 = (so[0] / (float)H_) * SO_;
        const float so1 = (so[1] / (float)H_) * SO_;
        float m0f[UPT_], m1f[UPT_], n0f[UPT_], n1f[UPT_], wo0f[UPT_], wo1f[UPT_];
        float negmc[UPT_];                 // -(MAGIC)*(m0f+m1f): cancels carried bias
        #pragma unroll
        for (int j = 0; j < UPT_; ++j) {
            const int k = k0 + j;
            m0f[j]  = m[k * 2 + 0] * cm;        m1f[j]  = m[k * 2 + 1] * cm;
            n0f[j]  = n[k * 2 + 0] * SA_;       n1f[j]  = n[k * 2 + 1] * SA_;
            wo0f[j] = wo[k * 2 + 0] * so0;      wo1f[j] = wo[k * 2 + 1] * so1;
            negmc[j] = -MAGIC_F * (m0f[j] + m1f[j]);
        }

        float h[UPT_];
        {
            const float4 hh = *(const float4*)(h0 + k0);
            h[0] = hh.x; h[1] = hh.y; h[2] = hh.z; h[3] = hh.w;
        }
        float*  traj_base = traj + (size_t)b * T_ * H_ + k0;
        float*  out_base  = out  + (size_t)b * T_ * O_;

        // prologue: biased a(0) from r = tanh(h0)
        float A0b, A1b;
        {
            float pa0 = 0.0f, pa1 = 0.0f;
            #pragma unroll
            for (int u = 0; u < UPT_; ++u) {
                const float r = tanh_mufu(h[u]);
                pa0 = fmaf(r, n0f[u], pa0);
                pa1 = fmaf(r, n1f[u], pa1);
            }
            const int W0 = redux_add_s32(__float_as_int(pa0 + MAGIC_F));
            const int W1 = redux_add_s32(__float_as_int(pa1 + MAGIC_F));
            if (lane == 0) s_red[1][warp] = make_int4(W0, W1, 0, 0);
        }
        cta_bar();                          // prologue barrier (matches producer)
        {
            int sx = 0, sy = 0;
            #pragma unroll
            for (int w = 0; w < NCW_; ++w) {
                const int4 v = s_red[1][w];
                sx += v.x; sy += v.y;
            }
            A0b = __int_as_float(sx + REBIAS_I);
            A1b = __int_as_float(sy + REBIAS_I);
        }
        float4 eR = *(const float4*)&s_e[0][k0];   // e(0), written pre-bar

        #pragma unroll 4
        for (int t = 0; t < T_; ++t) {
            const float ea[UPT_] = {eR.x, eR.y, eR.z, eR.w};

            // h' = 0.8h + e + a0*m0 + a1*m1 (bias via negmc) ; r' = tanh(h')
            float pa0 = 0.0f, pa1 = 0.0f, po0 = 0.0f, po1 = 0.0f;
            #pragma unroll
            for (int u = 0; u < UPT_; ++u) {
                const float hb = fmaf(1.0f - ALPHA_, h[u], ea[u] + negmc[u]);
                float hx = fmaf(A0b, m0f[u], hb);          // crit path: 2 FMA
                hx       = fmaf(A1b, m1f[u], hx);
                h[u] = hx;
                const float r = tanh_mufu(hx);             // 1 MUFU
                pa0 = fmaf(r, n0f[u], pa0);
                pa1 = fmaf(r, n1f[u], pa1);
                po0 = fmaf(r, wo0f[u], po0);
                po1 = fmaf(r, wo1f[u], po1);
            }

            // traj[t] = h_{t+1} (R4 position)
            *(float4*)(traj_base + (size_t)t * H_) =
                make_float4(h[0], h[1], h[2], h[3]);

            // warp reductions: magic-bias a-pair; plain F2I o-pair
            const int W0 = redux_add_s32(__float_as_int(pa0 + MAGIC_F));
            const int W1 = redux_add_s32(__float_as_int(pa1 + MAGIC_F));
            const int U0 = redux_add_s32(__float2int_rn(po0));
            const int U1 = redux_add_s32(__float2int_rn(po1));
            const int buf = t & 1;
            if (lane == 0) s_red[buf][warp] = make_int4(W0, W1, U0, U1);

            cta_bar();                      // per-step barrier

            // combine + e prefetch for t+1 (slot ordered by >=1 barrier)
            const int4 v0 = s_red[buf][0];
            const int4 v1 = s_red[buf][1];
            const int4 v2 = s_red[buf][2];
            const int4 v3 = s_red[buf][3];
            A0b = __int_as_float(((v0.x + v1.x) + (v2.x + v3.x)) + REBIAS_I);
            A1b = __int_as_float(((v0.y + v1.y) + (v2.y + v3.y)) + REBIAS_I);
            eR = *(const float4*)&s_e[(t + 1) & (RING_ - 1)][k0];

            if (tid == 0) {
                const float o0 = (float)((v0.z + v1.z) + (v2.z + v3.z)) * (1.0f / SO_);
                const float o1 = (float)((v0.w + v1.w) + (v2.w + v3.w)) * (1.0f / SO_);
                *(float2*)(out_base + (size_t)t * O_) = make_float2(o0, o1);
            }
        }
    }
}

extern "C" void kernel_launch(void* const* d_in, const int* in_sizes, int n_in,
                              void* d_out, int out_size) {
    const float* input = (const float*)d_in[0];
    const float* noise = (const float*)d_in[1];
    const float* wi    = (const float*)d_in[2];
    const float* si    = (const float*)d_in[3];
    const float* m     = (const float*)d_in[4];
    const float* n     = (const float*)d_in[5];
    const float* wo    = (const float*)d_in[6];
    const float* so    = (const float*)d_in[7];
    const float* h0    = (const float*)d_in[8];

    float* out  = (float*)d_out;                         // (B,T,O) first
    float* traj = (float*)d_out + (size_t)B_ * T_ * O_;  // then (B,T,H)

    lowrank_rnn_kernel<<<B_, NT_>>>(input, noise, wi, si, m, n, wo, so, h0,
                                    out, traj);
}

// round 13
// speedup vs baseline: 1.6109x; 1.1744x over previous
#include <cuda_runtime.h>
#include <cuda_bf16.h>

#define B_ 64
#define T_ 1024
#define I_ 8
#define H_ 512
#define O_ 2
#define NOISE_STD_ 0.05f
#define ALPHA_ 0.2f

#define NT_   160           // 5 warps: wid3 = consumer (alone on SMSP3), rest producers
#define RING_ 16            // e-ring slots (32 KB smem)

#define SA_      8192.0f    // 2^13 scale for recurrence dots (window-proven R6/R11/R12)
#define SO_      2097152.0f // 2^21 scale for output dots
#define MAGIC_F  12582912.0f        // 2^23 + 2^22 round-to-int bias
// Single-warp REDUX of 32 biased floats: bias total = 32*0x4B400000 mod 2^32
// = 0x68000000. Re-bias: + (0x4B400000 - 0x68000000) = 0xE3400000.
#define REBIAS_I ((int)0xE3400000u)

__device__ __forceinline__ float tanh_mufu(float x) {
    float r; asm("tanh.approx.f32 %0, %1;" : "=f"(r) : "f"(x)); return r;
}
__device__ __forceinline__ int redux_add_s32(int v) {
    int r; asm volatile("redux.sync.add.s32 %0, %1, 0xffffffff;" : "=r"(r) : "r"(v)); return r;
}
// Fresh 128-bit smem load (compiler may not cache; producer data race-free by counters)
__device__ __forceinline__ float4 ldsv4(const float* p) {
    float4 v;
    unsigned a = (unsigned)__cvta_generic_to_shared(p);
    asm volatile("ld.volatile.shared.v4.f32 {%0,%1,%2,%3}, [%4];"
                 : "=f"(v.x), "=f"(v.y), "=f"(v.z), "=f"(v.w) : "r"(a));
    return v;
}

__global__ __launch_bounds__(NT_, 1)
void lowrank_rnn_kernel(const float* __restrict__ input,   // (B,T,I)
                        const float* __restrict__ noise,   // (B,T,H)
                        const float* __restrict__ wi,      // (I,H)
                        const float* __restrict__ si,      // (I,)
                        const float* __restrict__ m,       // (H,R)
                        const float* __restrict__ n,       // (H,R)
                        const float* __restrict__ wo,      // (H,O)
                        const float* __restrict__ so,      // (O,)
                        const float* __restrict__ h0,      // (H,)
                        float* __restrict__ out,           // (B,T,O)
                        float* __restrict__ traj)          // (B,T,H)
{
    __shared__ float s_e[RING_][H_];       // e(t) = 0.05nz + alpha*proj + negmc
    __shared__ volatile int s_pcnt[4];     // per-producer-warp: produced-through step
    __shared__ volatile int s_ccnt;        // consumer published progress

    const int b    = blockIdx.x;
    const int tid  = threadIdx.x;
    const int w    = tid >> 5;
    const int lane = tid & 31;

    const float cm = (ALPHA_ / (float)H_) / SA_;   // alpha/H and 1/Sa folded into m

    if (w != 3) {
        // =================== PRODUCER (warps 0,1,2,4) ===================
        const int pw   = (w < 3) ? w : 3;
        const int ptid = pw * 32 + lane;
        const int k0   = ptid * 4;                 // 4 units per producer thread

        float wif[I_][4];                          // wi * si * alpha
        #pragma unroll
        for (int i = 0; i < I_; ++i) {
            const float4 ww = *(const float4*)(wi + i * H_ + k0);
            const float  s  = si[i] * ALPHA_;
            wif[i][0] = ww.x * s; wif[i][1] = ww.y * s;
            wif[i][2] = ww.z * s; wif[i][3] = ww.w * s;
        }
        float negmc[4];                            // -MAGIC*(m0f+m1f), folded into e
        {
            const float4 mA = *(const float4*)(m + k0 * 2);
            const float4 mB = *(const float4*)(m + k0 * 2 + 4);
            negmc[0] = -MAGIC_F * (mA.x * cm + mA.y * cm);
            negmc[1] = -MAGIC_F * (mA.z * cm + mA.w * cm);
            negmc[2] = -MAGIC_F * (mB.x * cm + mB.y * cm);
            negmc[3] = -MAGIC_F * (mB.z * cm + mB.w * cm);
        }
        const float* nz_base = noise + (size_t)b * T_ * H_ + k0;
        const float* in_base = input + (size_t)b * T_ * I_;

        // prologue: produce steps 0..7 directly
        for (int s = 0; s < 8; ++s) {
            const float4 nz = *(const float4*)(nz_base + (size_t)s * H_);
            const float4 x0 = __ldg((const float4*)(in_base + s * I_));
            const float4 x1 = __ldg((const float4*)(in_base + s * I_ + 4));
            const float nza[4] = {nz.x, nz.y, nz.z, nz.w};
            float e[4];
            #pragma unroll
            for (int u = 0; u < 4; ++u) {
                float pp = fmaf(NOISE_STD_, nza[u], negmc[u]);
                pp = fmaf(x0.x, wif[0][u], pp);
                pp = fmaf(x0.y, wif[1][u], pp);
                pp = fmaf(x0.z, wif[2][u], pp);
                pp = fmaf(x0.w, wif[3][u], pp);
                pp = fmaf(x1.x, wif[4][u], pp);
                pp = fmaf(x1.y, wif[5][u], pp);
                pp = fmaf(x1.z, wif[6][u], pp);
                pp = fmaf(x1.w, wif[7][u], pp);
                e[u] = pp;
            }
            *(float4*)&s_e[s][k0] = make_float4(e[0], e[1], e[2], e[3]);
        }
        if (lane == 0) { s_pcnt[pw] = 8; if (pw == 0) s_ccnt = 0; }

        // preload LDG ring for steps 8..11
        float4 rnz[4], rx0[4], rx1[4];
        #pragma unroll
        for (int j = 0; j < 4; ++j) {
            const int t = 8 + j;
            rnz[j] = *(const float4*)(nz_base + (size_t)t * H_);
            rx0[j] = __ldg((const float4*)(in_base + t * I_));
            rx1[j] = __ldg((const float4*)(in_base + t * I_ + 4));
        }
        __syncthreads();                           // the ONLY CTA barrier

        int cons = 0;
        #pragma unroll 4
        for (int tp = 8; tp < T_; ++tp) {
            // backpressure: slot reuse safe if tp <= cons_published + 12 (ring 16)
            if (tp > cons + 12) {
                cons = s_ccnt;
                while (tp > cons + 12) { __nanosleep(200); cons = s_ccnt; }
            }
            const int j = tp & 3;
            const float4 nz = rnz[j];
            const float4 x0 = rx0[j];
            const float4 x1 = rx1[j];
            int tl = tp + 4; if (tl > T_ - 1) tl = T_ - 1;
            rnz[j] = *(const float4*)(nz_base + (size_t)tl * H_);
            rx0[j] = __ldg((const float4*)(in_base + tl * I_));
            rx1[j] = __ldg((const float4*)(in_base + tl * I_ + 4));

            const float nza[4] = {nz.x, nz.y, nz.z, nz.w};
            float e[4];
            #pragma unroll
            for (int u = 0; u < 4; ++u) {
                float pp = fmaf(NOISE_STD_, nza[u], negmc[u]);
                pp = fmaf(x0.x, wif[0][u], pp);
                pp = fmaf(x0.y, wif[1][u], pp);
                pp = fmaf(x0.z, wif[2][u], pp);
                pp = fmaf(x0.w, wif[3][u], pp);
                pp = fmaf(x1.x, wif[4][u], pp);
                pp = fmaf(x1.y, wif[5][u], pp);
                pp = fmaf(x1.z, wif[6][u], pp);
                pp = fmaf(x1.w, wif[7][u], pp);
                e[u] = pp;
            }
            *(float4*)&s_e[tp & (RING_ - 1)][k0] = make_float4(e[0], e[1], e[2], e[3]);

            if ((tp & 3) == 3) {                   // publish every 4 steps
                __threadfence_block();
                if (lane == 0) s_pcnt[pw] = tp + 1;
            }
        }
    } else {
        // =================== CONSUMER (warp 3, alone on SMSP3) ===================
        // lane owns units k = jb*128 + lane*4 + u  (jb,u in 0..3) => coalesced IO
        const float so0 = (so[0] / (float)H_) * SO_;
        const float so1 = (so[1] / (float)H_) * SO_;
        float m0f[16], m1f[16], n0f[16], n1f[16], wo0f[16], wo1f[16];
        float h[16];
        #pragma unroll
        for (int jb = 0; jb < 4; ++jb) {
            const int k0 = jb * 128 + lane * 4;
            const float4 mA = *(const float4*)(m + k0 * 2);
            const float4 mB = *(const float4*)(m + k0 * 2 + 4);
            const float4 nA = *(const float4*)(n + k0 * 2);
            const float4 nB = *(const float4*)(n + k0 * 2 + 4);
            const float4 wA = *(const float4*)(wo + k0 * 2);
            const float4 wB = *(const float4*)(wo + k0 * 2 + 4);
            const float4 hh = *(const float4*)(h0 + k0);
            const int q = jb * 4;
            m0f[q+0]=mA.x*cm; m1f[q+0]=mA.y*cm; m0f[q+1]=mA.z*cm; m1f[q+1]=mA.w*cm;
            m0f[q+2]=mB.x*cm; m1f[q+2]=mB.y*cm; m0f[q+3]=mB.z*cm; m1f[q+3]=mB.w*cm;
            n0f[q+0]=nA.x*SA_; n1f[q+0]=nA.y*SA_; n0f[q+1]=nA.z*SA_; n1f[q+1]=nA.w*SA_;
            n0f[q+2]=nB.x*SA_; n1f[q+2]=nB.y*SA_; n0f[q+3]=nB.z*SA_; n1f[q+3]=nB.w*SA_;
            wo0f[q+0]=wA.x*so0; wo1f[q+0]=wA.y*so1; wo0f[q+1]=wA.z*so0; wo1f[q+1]=wA.w*so1;
            wo0f[q+2]=wB.x*so0; wo1f[q+2]=wB.y*so1; wo0f[q+3]=wB.z*so0; wo1f[q+3]=wB.w*so1;
            h[q+0]=hh.x; h[q+1]=hh.y; h[q+2]=hh.z; h[q+3]=hh.w;
        }
        float* traj_base = traj + (size_t)b * T_ * H_ + lane * 4;
        float* out_base  = out  + (size_t)b * T_ * O_;

        // a(0): single-warp magic REDUX, no smem exchange
        float A0b, A1b;
        {
            float pa0 = 0.0f, pa1 = 0.0f;
            #pragma unroll
            for (int q = 0; q < 16; ++q) {
                const float r = tanh_mufu(h[q]);
                pa0 = fmaf(r, n0f[q], pa0);
                pa1 = fmaf(r, n1f[q], pa1);
            }
            const int W0 = redux_add_s32(__float_as_int(pa0 + MAGIC_F));
            const int W1 = redux_add_s32(__float_as_int(pa1 + MAGIC_F));
            A0b = __int_as_float(W0 + REBIAS_I);
            A1b = __int_as_float(W1 + REBIAS_I);
        }
        __syncthreads();                           // matches producer prologue bar

        // stage e(0)
        float4 e4[4];
        #pragma unroll
        for (int jb = 0; jb < 4; ++jb)
            e4[jb] = ldsv4(&s_e[0][jb * 128 + lane * 4]);
        int avail = 8;

        #pragma unroll 2
        for (int t = 0; t < T_; ++t) {
            // h' = 0.8h + e + A0b*m0f + A1b*m1f (bias cancels via negmc in e)
            float ea[16];
            #pragma unroll
            for (int jb = 0; jb < 4; ++jb) {
                ea[jb*4+0]=e4[jb].x; ea[jb*4+1]=e4[jb].y;
                ea[jb*4+2]=e4[jb].z; ea[jb*4+3]=e4[jb].w;
            }
            #pragma unroll
            for (int q = 0; q < 16; ++q) {
                const float hb = fmaf(1.0f - ALPHA_, h[q], ea[q]);
                float hx = fmaf(A0b, m0f[q], hb);
                hx       = fmaf(A1b, m1f[q], hx);
                h[q] = hx;
            }
            // traj[t] = h_{t+1}, 4x STG.128 coalesced
            #pragma unroll
            for (int jb = 0; jb < 4; ++jb)
                *(float4*)(traj_base + (size_t)t * H_ + jb * 128) =
                    make_float4(h[jb*4+0], h[jb*4+1], h[jb*4+2], h[jb*4+3]);

            // tanh + dots (2 accumulation chains per dot: depth 8)
            float a0A=0.f, a0B=0.f, a1A=0.f, a1B=0.f;
            float o0A=0.f, o0B=0.f, o1A=0.f, o1B=0.f;
            #pragma unroll
            for (int q = 0; q < 8; ++q) {
                const float rA = tanh_mufu(h[q]);
                const float rB = tanh_mufu(h[q + 8]);
                a0A = fmaf(rA, n0f[q], a0A);      a0B = fmaf(rB, n0f[q+8], a0B);
                a1A = fmaf(rA, n1f[q], a1A);      a1B = fmaf(rB, n1f[q+8], a1B);
                o0A = fmaf(rA, wo0f[q], o0A);     o0B = fmaf(rB, wo0f[q+8], o0B);
                o1A = fmaf(rA, wo1f[q], o1A);     o1B = fmaf(rB, wo1f[q+8], o1B);
            }
            const int W0 = redux_add_s32(__float_as_int((a0A + a0B) + MAGIC_F));
            const int W1 = redux_add_s32(__float_as_int((a1A + a1B) + MAGIC_F));
            const int U0 = redux_add_s32(__float2int_rn(o0A + o0B));
            const int U1 = redux_add_s32(__float2int_rn(o1A + o1B));

            // prefetch e(t+1) while REDUX is in flight
            int tn = t + 1; if (tn > T_ - 1) tn = T_ - 1;
            if (avail <= tn) {
                do {
                    const int c0 = s_pcnt[0], c1 = s_pcnt[1];
                    const int c2 = s_pcnt[2], c3 = s_pcnt[3];
                    avail = min(min(c0, c1), min(c2, c3));
                } while (avail <= tn);
            }
            const int slot = tn & (RING_ - 1);
            #pragma unroll
            for (int jb = 0; jb < 4; ++jb)
                e4[jb] = ldsv4(&s_e[slot][jb * 128 + lane * 4]);

            // decode a(t+1) (magic re-bias, no I2F)
            A0b = __int_as_float(W0 + REBIAS_I);
            A1b = __int_as_float(W1 + REBIAS_I);

            if (lane == 0) {
                const float o0 = (float)U0 * (1.0f / SO_);
                const float o1 = (float)U1 * (1.0f / SO_);
                *(float2*)(out_base + (size_t)t * O_) = make_float2(o0, o1);
                if ((t & 7) == 7) s_ccnt = t + 1;   // publish progress
            }
        }
    }
}

extern "C" void kernel_launch(void* const* d_in, const int* in_sizes, int n_in,
                              void* d_out, int out_size) {
    const float* input = (const float*)d_in[0];
    const float* noise = (const float*)d_in[1];
    const float* wi    = (const float*)d_in[2];
    const float* si    = (const float*)d_in[3];
    const float* m     = (const float*)d_in[4];
    const float* n     = (const float*)d_in[5];
    const float* wo    = (const float*)d_in[6];
    const float* so    = (const float*)d_in[7];
    const float* h0    = (const float*)d_in[8];

    float* out  = (float*)d_out;                         // (B,T,O) first
    float* traj = (float*)d_out + (size_t)B_ * T_ * O_;  // then (B,T,H)

    lowrank_rnn_kernel<<<B_, NT_>>>(input, noise, wi, si, m, n, wo, so, h0,
                                    out, traj);
}